// round 4
// baseline (speedup 1.0000x reference)
#include <cuda_runtime.h>
#include <math.h>

// Problem constants
// B=8, N=1024, DIM=512, HEADS=8, DIM_HEAD=64, INNER=512
// M = B*N = 8192 rows

// Scratch (allocation-free: __device__ globals)
__device__ float g_q[64 * 1024 * 64];   // (bh, n, d)  16 MB
__device__ float g_k[64 * 1024 * 64];   // (bh, n, d)  16 MB
__device__ float g_v[64 * 1024 * 64];   // (bh, n, d)  16 MB
__device__ float g_ao[8192 * 512];      // (b*n, inner) 16 MB

// ---------------------------------------------------------------------------
// GEMM1: qkv = x(8192x512) @ w_qkv(512x1536), scatter into g_q/g_k/g_v
// Block tile 128x128, BK=8, 256 threads, 8x8 per-thread microtile.
// ---------------------------------------------------------------------------
__global__ __launch_bounds__(256) void gemm_qkv_kernel(
    const float* __restrict__ A, const float* __restrict__ Bw)
{
    __shared__ float As[8][128];
    __shared__ float Bs[8][128];
    const int bm = blockIdx.y * 128;
    const int bn = blockIdx.x * 128;
    const int tid = threadIdx.x;
    const int tx = tid & 15;        // n dim
    const int ty = tid >> 4;        // m dim

    float acc[8][8];
#pragma unroll
    for (int i = 0; i < 8; i++)
#pragma unroll
        for (int j = 0; j < 8; j++) acc[i][j] = 0.f;

    for (int k0 = 0; k0 < 512; k0 += 8) {
        {   // A tile 128x8: one float4 per thread, stored transposed
            int row = tid >> 1;
            int c = (tid & 1) * 4;
            float4 v = *reinterpret_cast<const float4*>(
                A + (size_t)(bm + row) * 512 + k0 + c);
            As[c + 0][row] = v.x; As[c + 1][row] = v.y;
            As[c + 2][row] = v.z; As[c + 3][row] = v.w;
        }
        {   // B tile 8x128: one float4 per thread
            int row = tid >> 5;
            int c = (tid & 31) * 4;
            float4 v = *reinterpret_cast<const float4*>(
                Bw + (size_t)(k0 + row) * 1536 + bn + c);
            *reinterpret_cast<float4*>(&Bs[row][c]) = v;
        }
        __syncthreads();
#pragma unroll
        for (int kk = 0; kk < 8; kk++) {
            float4 a0 = *reinterpret_cast<float4*>(&As[kk][ty * 8]);
            float4 a1 = *reinterpret_cast<float4*>(&As[kk][ty * 8 + 4]);
            float4 b0 = *reinterpret_cast<float4*>(&Bs[kk][tx * 8]);
            float4 b1 = *reinterpret_cast<float4*>(&Bs[kk][tx * 8 + 4]);
            float a[8] = {a0.x, a0.y, a0.z, a0.w, a1.x, a1.y, a1.z, a1.w};
            float b[8] = {b0.x, b0.y, b0.z, b0.w, b1.x, b1.y, b1.z, b1.w};
#pragma unroll
            for (int i = 0; i < 8; i++)
#pragma unroll
                for (int j = 0; j < 8; j++)
                    acc[i][j] = fmaf(a[i], b[j], acc[i][j]);
        }
        __syncthreads();
    }

    // Scatter. Column block [bn, bn+128) stays inside one of q/k/v
    // (boundaries 512/1024 are multiples of 128). Each thread's 8-col strip
    // stays inside one 64-wide head (tx*8 mod 64 <= 56).
    const int col0 = bn + tx * 8;
    const int which = col0 >> 9;          // 0=q, 1=k, 2=v
    const int h = (col0 & 511) >> 6;      // head index
    const int d = col0 & 63;              // offset within head
    float* dst = (which == 0) ? g_q : (which == 1) ? g_k : g_v;
#pragma unroll
    for (int i = 0; i < 8; i++) {
        int m = bm + ty * 8 + i;
        int b = m >> 10, n = m & 1023;
        int bh = (b << 3) + h;
        float* drow = dst + ((size_t)(bh * 1024 + n)) * 64 + d;
        float4 w0 = {acc[i][0], acc[i][1], acc[i][2], acc[i][3]};
        float4 w1 = {acc[i][4], acc[i][5], acc[i][6], acc[i][7]};
        *reinterpret_cast<float4*>(drow)     = w0;
        *reinterpret_cast<float4*>(drow + 4) = w1;
    }
}

// ---------------------------------------------------------------------------
// Flash attention: one CTA per (bh, 64-query tile). Online softmax over 16
// key tiles of 64. Diagonal self-mask = -1e30 pre-softmax.
// smem: Qs[64][64], Ks[64][65], Vs[64][64], Ps[64][65]  = 66048 B dynamic
// ---------------------------------------------------------------------------
__global__ __launch_bounds__(256) void attn_kernel(const float* __restrict__ temp)
{
    extern __shared__ float sm[];
    float* Qs = sm;                 // stride 64
    float* Ks = Qs + 64 * 64;       // stride 65 (pad for K^T reads)
    float* Vs = Ks + 64 * 65;       // stride 64
    float* Ps = Vs + 64 * 64;       // stride 65

    const int qt = blockIdx.x;      // 0..15
    const int bh = blockIdx.y;      // 0..63
    const int tid = threadIdx.x;
    const int tx = tid & 15;
    const int ty = tid >> 4;
    const float scale = __expf(temp[0]);

    const float* qbase = g_q + ((size_t)(bh * 1024 + qt * 64)) * 64;
#pragma unroll
    for (int i = 0; i < 4; i++) {
        int f = tid + i * 256;      // float4 idx in [0,1024)
        int row = f >> 4;
        int c = (f & 15) * 4;
        float4 v = *reinterpret_cast<const float4*>(qbase + row * 64 + c);
        *reinterpret_cast<float4*>(&Qs[row * 64 + c]) = v;
    }

    float m_i[4], l_i[4], acc[4][4];
#pragma unroll
    for (int i = 0; i < 4; i++) {
        m_i[i] = -1e30f; l_i[i] = 0.f;
#pragma unroll
        for (int j = 0; j < 4; j++) acc[i][j] = 0.f;
    }

    for (int kt = 0; kt < 16; kt++) {
        __syncthreads();   // previous tile's Ps/Vs fully consumed
        const float* kbase = g_k + ((size_t)(bh * 1024 + kt * 64)) * 64;
        const float* vbase = g_v + ((size_t)(bh * 1024 + kt * 64)) * 64;
#pragma unroll
        for (int i = 0; i < 4; i++) {
            int f = tid + i * 256;
            int row = f >> 4;
            int c = (f & 15) * 4;
            float4 kv = *reinterpret_cast<const float4*>(kbase + row * 64 + c);
            Ks[row * 65 + c + 0] = kv.x;
            Ks[row * 65 + c + 1] = kv.y;
            Ks[row * 65 + c + 2] = kv.z;
            Ks[row * 65 + c + 3] = kv.w;
            float4 vv = *reinterpret_cast<const float4*>(vbase + row * 64 + c);
            *reinterpret_cast<float4*>(&Vs[row * 64 + c]) = vv;
        }
        __syncthreads();

        // S = Q K^T for this tile (each thread: 4 query rows x 4 key cols)
        float s[4][4];
#pragma unroll
        for (int i = 0; i < 4; i++)
#pragma unroll
            for (int j = 0; j < 4; j++) s[i][j] = 0.f;
#pragma unroll 8
        for (int k = 0; k < 64; k++) {
            float a[4], b4[4];
#pragma unroll
            for (int i = 0; i < 4; i++) a[i] = Qs[(ty * 4 + i) * 64 + k];
#pragma unroll
            for (int j = 0; j < 4; j++) b4[j] = Ks[(tx * 4 + j) * 65 + k];
#pragma unroll
            for (int i = 0; i < 4; i++)
#pragma unroll
                for (int j = 0; j < 4; j++)
                    s[i][j] = fmaf(a[i], b4[j], s[i][j]);
        }
#pragma unroll
        for (int i = 0; i < 4; i++)
#pragma unroll
            for (int j = 0; j < 4; j++) s[i][j] *= scale;
        if (qt == kt) {
#pragma unroll
            for (int i = 0; i < 4; i++)
#pragma unroll
                for (int j = 0; j < 4; j++)
                    if (ty * 4 + i == tx * 4 + j) s[i][j] = -1e30f;
        }

        // Online softmax update (row reductions across the 16 tx lanes)
#pragma unroll
        for (int i = 0; i < 4; i++) {
            float tm = fmaxf(fmaxf(s[i][0], s[i][1]), fmaxf(s[i][2], s[i][3]));
#pragma unroll
            for (int off = 8; off > 0; off >>= 1)
                tm = fmaxf(tm, __shfl_xor_sync(0xffffffffu, tm, off));
            float mn = fmaxf(m_i[i], tm);
            float alpha = __expf(m_i[i] - mn);
            m_i[i] = mn;
            float rs = 0.f;
#pragma unroll
            for (int j = 0; j < 4; j++) { s[i][j] = __expf(s[i][j] - mn); rs += s[i][j]; }
#pragma unroll
            for (int off = 8; off > 0; off >>= 1)
                rs += __shfl_xor_sync(0xffffffffu, rs, off);
            l_i[i] = l_i[i] * alpha + rs;
#pragma unroll
            for (int j = 0; j < 4; j++) {
                acc[i][j] *= alpha;
                Ps[(ty * 4 + i) * 65 + tx * 4 + j] = s[i][j];
            }
        }
        __syncthreads();

        // O += P V  (same 4x4 register tile; cols now = head dims)
#pragma unroll 8
        for (int k = 0; k < 64; k++) {
            float p[4], v4[4];
#pragma unroll
            for (int i = 0; i < 4; i++) p[i] = Ps[(ty * 4 + i) * 65 + k];
#pragma unroll
            for (int j = 0; j < 4; j++) v4[j] = Vs[k * 64 + tx * 4 + j];
#pragma unroll
            for (int i = 0; i < 4; i++)
#pragma unroll
                for (int j = 0; j < 4; j++)
                    acc[i][j] = fmaf(p[i], v4[j], acc[i][j]);
        }
    }

    // Normalize and write O in (b, n, h*64+d) layout
    const int b = bh >> 3, h = bh & 7;
#pragma unroll
    for (int i = 0; i < 4; i++) {
        float inv = 1.f / l_i[i];
        int qg = qt * 64 + ty * 4 + i;
        float* orow = g_ao + ((size_t)(b * 1024 + qg)) * 512 + h * 64;
#pragma unroll
        for (int j = 0; j < 4; j++) orow[tx * 4 + j] = acc[i][j] * inv;
    }
}

// ---------------------------------------------------------------------------
// GEMM2: out = g_ao(8192x512) @ w_out(512x512) + b_out
// Block tile 128x128, BK=8, 256 threads, 8x8 per-thread microtile.
// ---------------------------------------------------------------------------
__global__ __launch_bounds__(256) void gemm_out_kernel(
    const float* __restrict__ Bw, const float* __restrict__ bias,
    float* __restrict__ C)
{
    __shared__ float As[8][128];
    __shared__ float Bs[8][128];
    const int bm = blockIdx.y * 128;
    const int bn = blockIdx.x * 128;
    const int tid = threadIdx.x;
    const int tx = tid & 15;
    const int ty = tid >> 4;

    float acc[8][8];
#pragma unroll
    for (int i = 0; i < 8; i++)
#pragma unroll
        for (int j = 0; j < 8; j++) acc[i][j] = 0.f;

    for (int k0 = 0; k0 < 512; k0 += 8) {
        {
            int row = tid >> 1;
            int c = (tid & 1) * 4;
            float4 v = *reinterpret_cast<const float4*>(
                g_ao + (size_t)(bm + row) * 512 + k0 + c);
            As[c + 0][row] = v.x; As[c + 1][row] = v.y;
            As[c + 2][row] = v.z; As[c + 3][row] = v.w;
        }
        {
            int row = tid >> 5;
            int c = (tid & 31) * 4;
            float4 v = *reinterpret_cast<const float4*>(
                Bw + (size_t)(k0 + row) * 512 + bn + c);
            *reinterpret_cast<float4*>(&Bs[row][c]) = v;
        }
        __syncthreads();
#pragma unroll
        for (int kk = 0; kk < 8; kk++) {
            float4 a0 = *reinterpret_cast<float4*>(&As[kk][ty * 8]);
            float4 a1 = *reinterpret_cast<float4*>(&As[kk][ty * 8 + 4]);
            float4 b0 = *reinterpret_cast<float4*>(&Bs[kk][tx * 8]);
            float4 b1 = *reinterpret_cast<float4*>(&Bs[kk][tx * 8 + 4]);
            float a[8] = {a0.x, a0.y, a0.z, a0.w, a1.x, a1.y, a1.z, a1.w};
            float b[8] = {b0.x, b0.y, b0.z, b0.w, b1.x, b1.y, b1.z, b1.w};
#pragma unroll
            for (int i = 0; i < 8; i++)
#pragma unroll
                for (int j = 0; j < 8; j++)
                    acc[i][j] = fmaf(a[i], b[j], acc[i][j]);
        }
        __syncthreads();
    }

    const int cn = bn + tx * 8;
    float4 bi0 = *reinterpret_cast<const float4*>(bias + cn);
    float4 bi1 = *reinterpret_cast<const float4*>(bias + cn + 4);
#pragma unroll
    for (int i = 0; i < 8; i++) {
        int m = bm + ty * 8 + i;
        float* crow = C + (size_t)m * 512 + cn;
        float4 w0 = {acc[i][0] + bi0.x, acc[i][1] + bi0.y,
                     acc[i][2] + bi0.z, acc[i][3] + bi0.w};
        float4 w1 = {acc[i][4] + bi1.x, acc[i][5] + bi1.y,
                     acc[i][6] + bi1.z, acc[i][7] + bi1.w};
        *reinterpret_cast<float4*>(crow)     = w0;
        *reinterpret_cast<float4*>(crow + 4) = w1;
    }
}

// ---------------------------------------------------------------------------
extern "C" void kernel_launch(void* const* d_in, const int* in_sizes, int n_in,
                              void* d_out, int out_size)
{
    const float* x      = (const float*)d_in[0];   // (8,1024,512)
    const float* w_qkv  = (const float*)d_in[1];   // (512,1536)
    const float* temp   = (const float*)d_in[2];   // scalar
    const float* w_out  = (const float*)d_in[3];   // (512,512)
    const float* b_out  = (const float*)d_in[4];   // (512)
    float* out = (float*)d_out;                    // (8,1024,512)

    cudaFuncSetAttribute(attn_kernel,
                         cudaFuncAttributeMaxDynamicSharedMemorySize, 66048);

    gemm_qkv_kernel<<<dim3(12, 64), 256>>>(x, w_qkv);
    attn_kernel<<<dim3(16, 64), 256, 66048>>>(temp);
    gemm_out_kernel<<<dim3(4, 64), 256>>>(w_out, b_out, out);
}

// round 5
// speedup vs baseline: 2.1186x; 2.1186x over previous
#include <cuda_runtime.h>
#include <cuda_bf16.h>
#include <math.h>

// Problem constants: B=8, N=1024, DIM=512, HEADS=8, DIM_HEAD=64, INNER=512
// M = B*N = 8192

// -------------------- device scratch (no allocation) -----------------------
__device__ float g_q[64 * 1024 * 64];   // (bh, n, d) fp32
__device__ float g_k[64 * 1024 * 64];
__device__ float g_v[64 * 1024 * 64];

__device__ __nv_bfloat16 g_xh[8192 * 512];   // x split hi/lo
__device__ __nv_bfloat16 g_xl[8192 * 512];
__device__ __nv_bfloat16 g_w1h[1536 * 512];  // w_qkv^T split (K-major: [n][k])
__device__ __nv_bfloat16 g_w1l[1536 * 512];
__device__ __nv_bfloat16 g_w2h[512 * 512];   // w_out^T split
__device__ __nv_bfloat16 g_w2l[512 * 512];
__device__ __nv_bfloat16 g_aoh[8192 * 512];  // attention output split hi/lo
__device__ __nv_bfloat16 g_aol[8192 * 512];

// -------------------- mma.sync helper --------------------------------------
#define MMA16816(c, a, b)                                                     \
    asm volatile(                                                             \
        "mma.sync.aligned.m16n8k16.row.col.f32.bf16.bf16.f32 "                \
        "{%0,%1,%2,%3}, {%4,%5,%6,%7}, {%8,%9}, {%0,%1,%2,%3};"               \
        : "+f"((c)[0]), "+f"((c)[1]), "+f"((c)[2]), "+f"((c)[3])              \
        : "r"((a)[0]), "r"((a)[1]), "r"((a)[2]), "r"((a)[3]),                 \
          "r"((b)[0]), "r"((b)[1]))

// -------------------- prep: split x into bf16 hi/lo -------------------------
__global__ __launch_bounds__(256) void split_x_kernel(const float* __restrict__ X)
{
    int i = blockIdx.x * 256 + threadIdx.x;   // 4 elems per thread
    float4 v = *reinterpret_cast<const float4*>(X + (size_t)i * 4);
    float e[4] = {v.x, v.y, v.z, v.w};
#pragma unroll
    for (int j = 0; j < 4; j++) {
        __nv_bfloat16 h = __float2bfloat16(e[j]);
        g_xh[(size_t)i * 4 + j] = h;
        g_xl[(size_t)i * 4 + j] = __float2bfloat16(e[j] - __bfloat162float(h));
    }
}

// -------------------- prep: transpose + split weights -----------------------
// W is [512 k][ncols n]; output T*[n][512 k] bf16 hi/lo. which: 0 = w1, 1 = w2.
__global__ __launch_bounds__(256) void split_wT_kernel(const float* __restrict__ W,
                                                       int ncols, int which)
{
    __shared__ float tile[32][33];
    __nv_bfloat16* Th = which ? g_w2h : g_w1h;
    __nv_bfloat16* Tl = which ? g_w2l : g_w1l;
    const int no = blockIdx.x * 32;
    const int ko = blockIdx.y * 32;
    const int tx = threadIdx.x & 31;
    const int ty = threadIdx.x >> 5;    // 0..7
#pragma unroll
    for (int j = 0; j < 32; j += 8)
        tile[ty + j][tx] = W[(size_t)(ko + ty + j) * ncols + no + tx];
    __syncthreads();
#pragma unroll
    for (int j = 0; j < 32; j += 8) {
        int n = no + ty + j, k = ko + tx;
        float v = tile[tx][ty + j];
        __nv_bfloat16 h = __float2bfloat16(v);
        Th[(size_t)n * 512 + k] = h;
        Tl[(size_t)n * 512 + k] = __float2bfloat16(v - __bfloat162float(h));
    }
}

// -------------------- tensor-core GEMM mainloop -----------------------------
// 128x128 CTA tile, K=512, 8 warps (2 m x 4 n), warp tile 64x32.
// smem tiles 128 x 32 bf16, row pitch 40 elems (80 B) = conflict-free frags.
__device__ __forceinline__ void gemm_mainloop_bf16(
    const __nv_bfloat16* __restrict__ Ah, const __nv_bfloat16* __restrict__ Al,
    const __nv_bfloat16* __restrict__ Bh, const __nv_bfloat16* __restrict__ Bl,
    int bm, int bn,
    __nv_bfloat16* sAh, __nv_bfloat16* sAl,
    __nv_bfloat16* sBh, __nv_bfloat16* sBl,
    float acc[4][4][4])
{
    const int tid = threadIdx.x;
    const int wid = tid >> 5;
    const int lane = tid & 31;
    const int warpM = wid >> 2;          // 0..1
    const int warpN = wid & 3;           // 0..3
    const int g = lane >> 2;             // 0..7
    const int t = lane & 3;              // 0..3

    for (int kc = 0; kc < 512; kc += 32) {
#pragma unroll
        for (int it = 0; it < 2; it++) {
            int i = tid + it * 256;          // 0..511
            int row = i >> 2, seg = i & 3;
            int sidx = row * 40 + seg * 8;
            size_t ga = (size_t)(bm + row) * 512 + kc + seg * 8;
            size_t gb = (size_t)(bn + row) * 512 + kc + seg * 8;
            *reinterpret_cast<float4*>(&sAh[sidx]) =
                *reinterpret_cast<const float4*>(&Ah[ga]);
            *reinterpret_cast<float4*>(&sAl[sidx]) =
                *reinterpret_cast<const float4*>(&Al[ga]);
            *reinterpret_cast<float4*>(&sBh[sidx]) =
                *reinterpret_cast<const float4*>(&Bh[gb]);
            *reinterpret_cast<float4*>(&sBl[sidx]) =
                *reinterpret_cast<const float4*>(&Bl[gb]);
        }
        __syncthreads();
#pragma unroll
        for (int kk = 0; kk < 32; kk += 16) {
            unsigned ah[4][4], al[4][4], bh[4][2], bl[4][2];
#pragma unroll
            for (int tm = 0; tm < 4; tm++) {
                int r = warpM * 64 + tm * 16 + g;
                const __nv_bfloat16* p = &sAh[r * 40 + kk + 2 * t];
                const __nv_bfloat16* q = &sAl[r * 40 + kk + 2 * t];
                ah[tm][0] = *reinterpret_cast<const unsigned*>(p);
                ah[tm][1] = *reinterpret_cast<const unsigned*>(p + 8 * 40);
                ah[tm][2] = *reinterpret_cast<const unsigned*>(p + 8);
                ah[tm][3] = *reinterpret_cast<const unsigned*>(p + 8 * 40 + 8);
                al[tm][0] = *reinterpret_cast<const unsigned*>(q);
                al[tm][1] = *reinterpret_cast<const unsigned*>(q + 8 * 40);
                al[tm][2] = *reinterpret_cast<const unsigned*>(q + 8);
                al[tm][3] = *reinterpret_cast<const unsigned*>(q + 8 * 40 + 8);
            }
#pragma unroll
            for (int tn = 0; tn < 4; tn++) {
                int n = warpN * 32 + tn * 8 + g;
                const __nv_bfloat16* p = &sBh[n * 40 + kk + 2 * t];
                const __nv_bfloat16* q = &sBl[n * 40 + kk + 2 * t];
                bh[tn][0] = *reinterpret_cast<const unsigned*>(p);
                bh[tn][1] = *reinterpret_cast<const unsigned*>(p + 8);
                bl[tn][0] = *reinterpret_cast<const unsigned*>(q);
                bl[tn][1] = *reinterpret_cast<const unsigned*>(q + 8);
            }
#pragma unroll
            for (int tm = 0; tm < 4; tm++)
#pragma unroll
                for (int tn = 0; tn < 4; tn++) {
                    MMA16816(acc[tm][tn], ah[tm], bh[tn]);
                    MMA16816(acc[tm][tn], ah[tm], bl[tn]);
                    MMA16816(acc[tm][tn], al[tm], bh[tn]);
                }
        }
        __syncthreads();
    }
}

// -------------------- GEMM1: qkv, scatter to g_q/g_k/g_v --------------------
__global__ __launch_bounds__(256) void gemm_qkv_kernel()
{
    __shared__ __align__(16) __nv_bfloat16 sAh[128 * 40];
    __shared__ __align__(16) __nv_bfloat16 sAl[128 * 40];
    __shared__ __align__(16) __nv_bfloat16 sBh[128 * 40];
    __shared__ __align__(16) __nv_bfloat16 sBl[128 * 40];
    const int bm = blockIdx.y * 128;
    const int bn = blockIdx.x * 128;

    float acc[4][4][4];
#pragma unroll
    for (int a = 0; a < 4; a++)
#pragma unroll
        for (int b = 0; b < 4; b++)
#pragma unroll
            for (int c = 0; c < 4; c++) acc[a][b][c] = 0.f;

    gemm_mainloop_bf16(g_xh, g_xl, g_w1h, g_w1l, bm, bn,
                       sAh, sAl, sBh, sBl, acc);

    const int wid = threadIdx.x >> 5, lane = threadIdx.x & 31;
    const int warpM = wid >> 2, warpN = wid & 3;
    const int g = lane >> 2, t = lane & 3;
#pragma unroll
    for (int tm = 0; tm < 4; tm++)
#pragma unroll
        for (int tn = 0; tn < 4; tn++) {
            int m0 = bm + warpM * 64 + tm * 16 + g;
            int col0 = bn + warpN * 32 + tn * 8 + 2 * t;
            int which = col0 >> 9;
            int h = (col0 & 511) >> 6;
            int d = col0 & 63;
            float* dst = (which == 0) ? g_q : (which == 1) ? g_k : g_v;
            int b0 = m0 >> 10, n0 = m0 & 1023;
            int bh0 = (b0 << 3) + h;
            float2 v0 = {acc[tm][tn][0], acc[tm][tn][1]};
            float2 v1 = {acc[tm][tn][2], acc[tm][tn][3]};
            *reinterpret_cast<float2*>(dst + ((size_t)(bh0 * 1024 + n0)) * 64 + d) = v0;
            *reinterpret_cast<float2*>(dst + ((size_t)(bh0 * 1024 + n0 + 8)) * 64 + d) = v1;
        }
}

// -------------------- GEMM2: out projection + bias --------------------------
__global__ __launch_bounds__(256) void gemm_out_kernel(
    const float* __restrict__ bias, float* __restrict__ C)
{
    __shared__ __align__(16) __nv_bfloat16 sAh[128 * 40];
    __shared__ __align__(16) __nv_bfloat16 sAl[128 * 40];
    __shared__ __align__(16) __nv_bfloat16 sBh[128 * 40];
    __shared__ __align__(16) __nv_bfloat16 sBl[128 * 40];
    const int bm = blockIdx.y * 128;
    const int bn = blockIdx.x * 128;

    float acc[4][4][4];
#pragma unroll
    for (int a = 0; a < 4; a++)
#pragma unroll
        for (int b = 0; b < 4; b++)
#pragma unroll
            for (int c = 0; c < 4; c++) acc[a][b][c] = 0.f;

    gemm_mainloop_bf16(g_aoh, g_aol, g_w2h, g_w2l, bm, bn,
                       sAh, sAl, sBh, sBl, acc);

    const int wid = threadIdx.x >> 5, lane = threadIdx.x & 31;
    const int warpM = wid >> 2, warpN = wid & 3;
    const int g = lane >> 2, t = lane & 3;
#pragma unroll
    for (int tm = 0; tm < 4; tm++)
#pragma unroll
        for (int tn = 0; tn < 4; tn++) {
            int m0 = bm + warpM * 64 + tm * 16 + g;
            int col0 = bn + warpN * 32 + tn * 8 + 2 * t;
            float b0v = bias[col0], b1v = bias[col0 + 1];
            float2 v0 = {acc[tm][tn][0] + b0v, acc[tm][tn][1] + b1v};
            float2 v1 = {acc[tm][tn][2] + b0v, acc[tm][tn][3] + b1v};
            *reinterpret_cast<float2*>(C + (size_t)m0 * 512 + col0) = v0;
            *reinterpret_cast<float2*>(C + (size_t)(m0 + 8) * 512 + col0) = v1;
        }
}

// -------------------- flash attention (fp32, unchanged mainloop) ------------
__global__ __launch_bounds__(256) void attn_kernel(const float* __restrict__ temp)
{
    extern __shared__ float sm[];
    float* Qs = sm;                 // stride 64
    float* Ks = Qs + 64 * 64;       // stride 65
    float* Vs = Ks + 64 * 65;       // stride 64
    float* Ps = Vs + 64 * 64;       // stride 65

    const int qt = blockIdx.x;
    const int bh = blockIdx.y;
    const int tid = threadIdx.x;
    const int tx = tid & 15;
    const int ty = tid >> 4;
    const float scale = __expf(temp[0]);

    const float* qbase = g_q + ((size_t)(bh * 1024 + qt * 64)) * 64;
#pragma unroll
    for (int i = 0; i < 4; i++) {
        int f = tid + i * 256;
        int row = f >> 4;
        int c = (f & 15) * 4;
        float4 v = *reinterpret_cast<const float4*>(qbase + row * 64 + c);
        *reinterpret_cast<float4*>(&Qs[row * 64 + c]) = v;
    }

    float m_i[4], l_i[4], acc[4][4];
#pragma unroll
    for (int i = 0; i < 4; i++) {
        m_i[i] = -1e30f; l_i[i] = 0.f;
#pragma unroll
        for (int j = 0; j < 4; j++) acc[i][j] = 0.f;
    }

    for (int kt = 0; kt < 16; kt++) {
        __syncthreads();
        const float* kbase = g_k + ((size_t)(bh * 1024 + kt * 64)) * 64;
        const float* vbase = g_v + ((size_t)(bh * 1024 + kt * 64)) * 64;
#pragma unroll
        for (int i = 0; i < 4; i++) {
            int f = tid + i * 256;
            int row = f >> 4;
            int c = (f & 15) * 4;
            float4 kv = *reinterpret_cast<const float4*>(kbase + row * 64 + c);
            Ks[row * 65 + c + 0] = kv.x;
            Ks[row * 65 + c + 1] = kv.y;
            Ks[row * 65 + c + 2] = kv.z;
            Ks[row * 65 + c + 3] = kv.w;
            float4 vv = *reinterpret_cast<const float4*>(vbase + row * 64 + c);
            *reinterpret_cast<float4*>(&Vs[row * 64 + c]) = vv;
        }
        __syncthreads();

        float s[4][4];
#pragma unroll
        for (int i = 0; i < 4; i++)
#pragma unroll
            for (int j = 0; j < 4; j++) s[i][j] = 0.f;
#pragma unroll 8
        for (int k = 0; k < 64; k++) {
            float a[4], b4[4];
#pragma unroll
            for (int i = 0; i < 4; i++) a[i] = Qs[(ty * 4 + i) * 64 + k];
#pragma unroll
            for (int j = 0; j < 4; j++) b4[j] = Ks[(tx * 4 + j) * 65 + k];
#pragma unroll
            for (int i = 0; i < 4; i++)
#pragma unroll
                for (int j = 0; j < 4; j++)
                    s[i][j] = fmaf(a[i], b4[j], s[i][j]);
        }
#pragma unroll
        for (int i = 0; i < 4; i++)
#pragma unroll
            for (int j = 0; j < 4; j++) s[i][j] *= scale;
        if (qt == kt) {
#pragma unroll
            for (int i = 0; i < 4; i++)
#pragma unroll
                for (int j = 0; j < 4; j++)
                    if (ty * 4 + i == tx * 4 + j) s[i][j] = -1e30f;
        }

#pragma unroll
        for (int i = 0; i < 4; i++) {
            float tm = fmaxf(fmaxf(s[i][0], s[i][1]), fmaxf(s[i][2], s[i][3]));
#pragma unroll
            for (int off = 8; off > 0; off >>= 1)
                tm = fmaxf(tm, __shfl_xor_sync(0xffffffffu, tm, off));
            float mn = fmaxf(m_i[i], tm);
            float alpha = __expf(m_i[i] - mn);
            m_i[i] = mn;
            float rs = 0.f;
#pragma unroll
            for (int j = 0; j < 4; j++) { s[i][j] = __expf(s[i][j] - mn); rs += s[i][j]; }
#pragma unroll
            for (int off = 8; off > 0; off >>= 1)
                rs += __shfl_xor_sync(0xffffffffu, rs, off);
            l_i[i] = l_i[i] * alpha + rs;
#pragma unroll
            for (int j = 0; j < 4; j++) {
                acc[i][j] *= alpha;
                Ps[(ty * 4 + i) * 65 + tx * 4 + j] = s[i][j];
            }
        }
        __syncthreads();

#pragma unroll 8
        for (int k = 0; k < 64; k++) {
            float p[4], v4[4];
#pragma unroll
            for (int i = 0; i < 4; i++) p[i] = Ps[(ty * 4 + i) * 65 + k];
#pragma unroll
            for (int j = 0; j < 4; j++) v4[j] = Vs[k * 64 + tx * 4 + j];
#pragma unroll
            for (int i = 0; i < 4; i++)
#pragma unroll
                for (int j = 0; j < 4; j++)
                    acc[i][j] = fmaf(p[i], v4[j], acc[i][j]);
        }
    }

    // epilogue: write bf16 hi/lo split of attention output
    const int b = bh >> 3, h = bh & 7;
#pragma unroll
    for (int i = 0; i < 4; i++) {
        float inv = 1.f / l_i[i];
        int qg = qt * 64 + ty * 4 + i;
        size_t base = ((size_t)(b * 1024 + qg)) * 512 + h * 64 + tx * 4;
#pragma unroll
        for (int j = 0; j < 4; j++) {
            float o = acc[i][j] * inv;
            __nv_bfloat16 hh = __float2bfloat16(o);
            g_aoh[base + j] = hh;
            g_aol[base + j] = __float2bfloat16(o - __bfloat162float(hh));
        }
    }
}

// ---------------------------------------------------------------------------
extern "C" void kernel_launch(void* const* d_in, const int* in_sizes, int n_in,
                              void* d_out, int out_size)
{
    const float* x      = (const float*)d_in[0];   // (8,1024,512)
    const float* w_qkv  = (const float*)d_in[1];   // (512,1536)
    const float* temp   = (const float*)d_in[2];   // scalar
    const float* w_out  = (const float*)d_in[3];   // (512,512)
    const float* b_out  = (const float*)d_in[4];   // (512)
    float* out = (float*)d_out;                    // (8,1024,512)

    cudaFuncSetAttribute(attn_kernel,
                         cudaFuncAttributeMaxDynamicSharedMemorySize, 66048);

    split_x_kernel<<<4096, 256>>>(x);                          // 8192*512/4/256
    split_wT_kernel<<<dim3(48, 16), 256>>>(w_qkv, 1536, 0);
    split_wT_kernel<<<dim3(16, 16), 256>>>(w_out, 512, 1);
    gemm_qkv_kernel<<<dim3(12, 64), 256>>>();
    attn_kernel<<<dim3(16, 64), 256, 66048>>>(temp);
    gemm_out_kernel<<<dim3(4, 64), 256>>>(b_out, out);
}

// round 10
// speedup vs baseline: 3.3600x; 1.5860x over previous
#include <cuda_runtime.h>
#include <cuda_bf16.h>
#include <math.h>

// Problem constants: B=8, N=1024, DIM=512, HEADS=8, DIM_HEAD=64, INNER=512
// M = B*N = 8192

// -------------------- device scratch (no allocation) -----------------------
__device__ __nv_bfloat16 g_xh[8192 * 512];   // x split hi/lo
__device__ __nv_bfloat16 g_xl[8192 * 512];
__device__ __nv_bfloat16 g_w1h[1536 * 512];  // w_qkv^T split (K-major: [n][k])
__device__ __nv_bfloat16 g_w1l[1536 * 512];
__device__ __nv_bfloat16 g_w2h[512 * 512];   // w_out^T split
__device__ __nv_bfloat16 g_w2l[512 * 512];
__device__ __nv_bfloat16 g_aoh[8192 * 512];  // attention output split hi/lo
__device__ __nv_bfloat16 g_aol[8192 * 512];

__device__ __nv_bfloat16 g_qh[64 * 1024 * 64];  // (bh, n, d) bf16 hi/lo
__device__ __nv_bfloat16 g_ql[64 * 1024 * 64];
__device__ __nv_bfloat16 g_kh[64 * 1024 * 64];
__device__ __nv_bfloat16 g_kl[64 * 1024 * 64];
__device__ __nv_bfloat16 g_vth[64 * 64 * 1024]; // (bh, d, n)  V transposed
__device__ __nv_bfloat16 g_vtl[64 * 64 * 1024];

// -------------------- mma.sync helper --------------------------------------
#define MMA16816(c, a, b)                                                     \
    asm volatile(                                                             \
        "mma.sync.aligned.m16n8k16.row.col.f32.bf16.bf16.f32 "                \
        "{%0,%1,%2,%3}, {%4,%5,%6,%7}, {%8,%9}, {%0,%1,%2,%3};"               \
        : "+f"((c)[0]), "+f"((c)[1]), "+f"((c)[2]), "+f"((c)[3])              \
        : "r"((a)[0]), "r"((a)[1]), "r"((a)[2]), "r"((a)[3]),                 \
          "r"((b)[0]), "r"((b)[1]))

__device__ __forceinline__ void cp_async16(void* sdst, const void* gsrc)
{
    unsigned s = (unsigned)__cvta_generic_to_shared(sdst);
    asm volatile("cp.async.cg.shared.global [%0], [%1], 16;\n" :: "r"(s), "l"(gsrc));
}
#define CP_COMMIT() asm volatile("cp.async.commit_group;\n" ::: "memory")
#define CP_WAIT0()  asm volatile("cp.async.wait_group 0;\n" ::: "memory")

// -------------------- prep: split x into bf16 hi/lo -------------------------
__global__ __launch_bounds__(256) void split_x_kernel(const float* __restrict__ X)
{
    int i = blockIdx.x * 256 + threadIdx.x;   // 4 elems per thread
    float4 v = *reinterpret_cast<const float4*>(X + (size_t)i * 4);
    float e[4] = {v.x, v.y, v.z, v.w};
#pragma unroll
    for (int j = 0; j < 4; j++) {
        __nv_bfloat16 h = __float2bfloat16(e[j]);
        g_xh[(size_t)i * 4 + j] = h;
        g_xl[(size_t)i * 4 + j] = __float2bfloat16(e[j] - __bfloat162float(h));
    }
}

// -------------------- prep: transpose + split weights -----------------------
__global__ __launch_bounds__(256) void split_wT_kernel(const float* __restrict__ W,
                                                       int ncols, int which)
{
    __shared__ float tile[32][33];
    __nv_bfloat16* Th = which ? g_w2h : g_w1h;
    __nv_bfloat16* Tl = which ? g_w2l : g_w1l;
    const int no = blockIdx.x * 32;
    const int ko = blockIdx.y * 32;
    const int tx = threadIdx.x & 31;
    const int ty = threadIdx.x >> 5;
#pragma unroll
    for (int j = 0; j < 32; j += 8)
        tile[ty + j][tx] = W[(size_t)(ko + ty + j) * ncols + no + tx];
    __syncthreads();
#pragma unroll
    for (int j = 0; j < 32; j += 8) {
        int n = no + ty + j, k = ko + tx;
        float v = tile[tx][ty + j];
        __nv_bfloat16 h = __float2bfloat16(v);
        Th[(size_t)n * 512 + k] = h;
        Tl[(size_t)n * 512 + k] = __float2bfloat16(v - __bfloat162float(h));
    }
}

// -------------------- tensor-core GEMM mainloop (double-buffered) -----------
// 128x128 CTA tile, K=512, 8 warps (2 m x 4 n), warp tile 64x32.
// 2-stage cp.async pipeline: wait(i) -> sync -> issue(i+1) -> compute(i).
#define GSTAGE (4 * 128 * 40)           // elems per stage
#define GEMM_SMEM (2 * GSTAGE * 2)      // bytes = 81920

__device__ __forceinline__ void gemm_issue_tile(
    const __nv_bfloat16* __restrict__ Ah, const __nv_bfloat16* __restrict__ Al,
    const __nv_bfloat16* __restrict__ Bh, const __nv_bfloat16* __restrict__ Bl,
    int bm, int bn, int kc, __nv_bfloat16* base)
{
    const int tid = threadIdx.x;
#pragma unroll
    for (int it = 0; it < 2; it++) {
        int i = tid + it * 256;
        int row = i >> 2, seg = i & 3;
        int sidx = row * 40 + seg * 8;
        size_t ga = (size_t)(bm + row) * 512 + kc + seg * 8;
        size_t gb = (size_t)(bn + row) * 512 + kc + seg * 8;
        cp_async16(base + sidx,                Ah + ga);
        cp_async16(base + 128 * 40 + sidx,     Al + ga);
        cp_async16(base + 2 * 128 * 40 + sidx, Bh + gb);
        cp_async16(base + 3 * 128 * 40 + sidx, Bl + gb);
    }
    CP_COMMIT();
}

__device__ __forceinline__ void gemm_mainloop_bf16(
    const __nv_bfloat16* __restrict__ Ah, const __nv_bfloat16* __restrict__ Al,
    const __nv_bfloat16* __restrict__ Bh, const __nv_bfloat16* __restrict__ Bl,
    int bm, int bn, __nv_bfloat16* sm, float acc[4][4][4])
{
    const int tid = threadIdx.x;
    const int wid = tid >> 5;
    const int lane = tid & 31;
    const int warpM = wid >> 2;
    const int warpN = wid & 3;
    const int g = lane >> 2;
    const int t = lane & 3;

    gemm_issue_tile(Ah, Al, Bh, Bl, bm, bn, 0, sm);

    for (int kc = 0; kc < 512; kc += 32) {
        const int st = (kc >> 5) & 1;
        CP_WAIT0();
        __syncthreads();
        if (kc + 32 < 512)
            gemm_issue_tile(Ah, Al, Bh, Bl, bm, bn, kc + 32, sm + (st ^ 1) * GSTAGE);

        __nv_bfloat16* sAh = sm + st * GSTAGE;
        __nv_bfloat16* sAl = sAh + 128 * 40;
        __nv_bfloat16* sBh = sAl + 128 * 40;
        __nv_bfloat16* sBl = sBh + 128 * 40;
#pragma unroll
        for (int kk = 0; kk < 32; kk += 16) {
            unsigned ah[4][4], al[4][4], bh[4][2], bl[4][2];
#pragma unroll
            for (int tm = 0; tm < 4; tm++) {
                int r = warpM * 64 + tm * 16 + g;
                const __nv_bfloat16* p = &sAh[r * 40 + kk + 2 * t];
                const __nv_bfloat16* q = &sAl[r * 40 + kk + 2 * t];
                ah[tm][0] = *reinterpret_cast<const unsigned*>(p);
                ah[tm][1] = *reinterpret_cast<const unsigned*>(p + 8 * 40);
                ah[tm][2] = *reinterpret_cast<const unsigned*>(p + 8);
                ah[tm][3] = *reinterpret_cast<const unsigned*>(p + 8 * 40 + 8);
                al[tm][0] = *reinterpret_cast<const unsigned*>(q);
                al[tm][1] = *reinterpret_cast<const unsigned*>(q + 8 * 40);
                al[tm][2] = *reinterpret_cast<const unsigned*>(q + 8);
                al[tm][3] = *reinterpret_cast<const unsigned*>(q + 8 * 40 + 8);
            }
#pragma unroll
            for (int tn = 0; tn < 4; tn++) {
                int n = warpN * 32 + tn * 8 + g;
                const __nv_bfloat16* p = &sBh[n * 40 + kk + 2 * t];
                const __nv_bfloat16* q = &sBl[n * 40 + kk + 2 * t];
                bh[tn][0] = *reinterpret_cast<const unsigned*>(p);
                bh[tn][1] = *reinterpret_cast<const unsigned*>(p + 8);
                bl[tn][0] = *reinterpret_cast<const unsigned*>(q);
                bl[tn][1] = *reinterpret_cast<const unsigned*>(q + 8);
            }
#pragma unroll
            for (int tm = 0; tm < 4; tm++)
#pragma unroll
                for (int tn = 0; tn < 4; tn++) {
                    MMA16816(acc[tm][tn], ah[tm], bh[tn]);
                    MMA16816(acc[tm][tn], ah[tm], bl[tn]);
                    MMA16816(acc[tm][tn], al[tm], bh[tn]);
                }
        }
        __syncthreads();
    }
}

// -------------------- GEMM1: qkv -> bf16 q/k + transposed v -----------------
__global__ __launch_bounds__(256) void gemm_qkv_kernel()
{
    extern __shared__ __align__(16) __nv_bfloat16 smg[];
    const int bm = blockIdx.y * 128;
    const int bn = blockIdx.x * 128;

    float acc[4][4][4];
#pragma unroll
    for (int a = 0; a < 4; a++)
#pragma unroll
        for (int b = 0; b < 4; b++)
#pragma unroll
            for (int c = 0; c < 4; c++) acc[a][b][c] = 0.f;

    gemm_mainloop_bf16(g_xh, g_xl, g_w1h, g_w1l, bm, bn, smg, acc);

    const int wid = threadIdx.x >> 5, lane = threadIdx.x & 31;
    const int warpM = wid >> 2, warpN = wid & 3;
    const int g = lane >> 2, t = lane & 3;
#pragma unroll
    for (int tm = 0; tm < 4; tm++)
#pragma unroll
        for (int tn = 0; tn < 4; tn++) {
            int m0 = bm + warpM * 64 + tm * 16 + g;
            int col0 = bn + warpN * 32 + tn * 8 + 2 * t;
            int which = col0 >> 9;
            int h = (col0 & 511) >> 6;
            int d = col0 & 63;
            int b0 = m0 >> 10, n0 = m0 & 1023;
            int bh0 = (b0 << 3) + h;
            float v00 = acc[tm][tn][0], v01 = acc[tm][tn][1];
            float v10 = acc[tm][tn][2], v11 = acc[tm][tn][3];
            __nv_bfloat16 h00 = __float2bfloat16(v00);
            __nv_bfloat16 h01 = __float2bfloat16(v01);
            __nv_bfloat16 h10 = __float2bfloat16(v10);
            __nv_bfloat16 h11 = __float2bfloat16(v11);
            __nv_bfloat16 l00 = __float2bfloat16(v00 - __bfloat162float(h00));
            __nv_bfloat16 l01 = __float2bfloat16(v01 - __bfloat162float(h01));
            __nv_bfloat16 l10 = __float2bfloat16(v10 - __bfloat162float(h10));
            __nv_bfloat16 l11 = __float2bfloat16(v11 - __bfloat162float(h11));
            if (which < 2) {
                __nv_bfloat16* dh = which ? g_kh : g_qh;
                __nv_bfloat16* dl = which ? g_kl : g_ql;
                size_t r0 = ((size_t)(bh0 * 1024 + n0)) * 64 + d;
                size_t r1 = ((size_t)(bh0 * 1024 + n0 + 8)) * 64 + d;
                *reinterpret_cast<__nv_bfloat162*>(dh + r0) = {h00, h01};
                *reinterpret_cast<__nv_bfloat162*>(dl + r0) = {l00, l01};
                *reinterpret_cast<__nv_bfloat162*>(dh + r1) = {h10, h11};
                *reinterpret_cast<__nv_bfloat162*>(dl + r1) = {l10, l11};
            } else {
                // V transposed: (bh, d, n)
                size_t c0 = ((size_t)(bh0 * 64 + d)) * 1024 + n0;
                size_t c1 = ((size_t)(bh0 * 64 + d + 1)) * 1024 + n0;
                g_vth[c0] = h00;     g_vtl[c0] = l00;
                g_vth[c1] = h01;     g_vtl[c1] = l01;
                g_vth[c0 + 8] = h10; g_vtl[c0 + 8] = l10;
                g_vth[c1 + 8] = h11; g_vtl[c1 + 8] = l11;
            }
        }
}

// -------------------- GEMM2: out projection + bias --------------------------
__global__ __launch_bounds__(256) void gemm_out_kernel(
    const float* __restrict__ bias, float* __restrict__ C)
{
    extern __shared__ __align__(16) __nv_bfloat16 smg[];
    const int bm = blockIdx.y * 128;
    const int bn = blockIdx.x * 128;

    float acc[4][4][4];
#pragma unroll
    for (int a = 0; a < 4; a++)
#pragma unroll
        for (int b = 0; b < 4; b++)
#pragma unroll
            for (int c = 0; c < 4; c++) acc[a][b][c] = 0.f;

    gemm_mainloop_bf16(g_aoh, g_aol, g_w2h, g_w2l, bm, bn, smg, acc);

    const int wid = threadIdx.x >> 5, lane = threadIdx.x & 31;
    const int warpM = wid >> 2, warpN = wid & 3;
    const int g = lane >> 2, t = lane & 3;
#pragma unroll
    for (int tm = 0; tm < 4; tm++)
#pragma unroll
        for (int tn = 0; tn < 4; tn++) {
            int m0 = bm + warpM * 64 + tm * 16 + g;
            int col0 = bn + warpN * 32 + tn * 8 + 2 * t;
            float b0v = bias[col0], b1v = bias[col0 + 1];
            float2 v0 = {acc[tm][tn][0] + b0v, acc[tm][tn][1] + b1v};
            float2 v1 = {acc[tm][tn][2] + b0v, acc[tm][tn][3] + b1v};
            *reinterpret_cast<float2*>(C + (size_t)m0 * 512 + col0) = v0;
            *reinterpret_cast<float2*>(C + (size_t)(m0 + 8) * 512 + col0) = v1;
        }
}

// -------------------- tensor-core flash attention ---------------------------
// One CTA per (bh, 128-query tile). 8 warps: warpM=wid>>1 (4 x 32 rows),
// warpN=wid&1 (2 x 32 cols). 64-key tiles, online softmax, split-bf16 MMA.
#define ATTN_SMEM 145920
__global__ __launch_bounds__(256) void attn_kernel(const float* __restrict__ temp)
{
    extern __shared__ char smraw[];
    __nv_bfloat16* sQh = reinterpret_cast<__nv_bfloat16*>(smraw);   // 128x72
    __nv_bfloat16* sQl = sQh + 128 * 72;
    __nv_bfloat16* sKh = sQl + 128 * 72;                            // 64x72
    __nv_bfloat16* sKl = sKh + 64 * 72;
    __nv_bfloat16* sVh = sKl + 64 * 72;                             // 64x72 (d, key)
    __nv_bfloat16* sVl = sVh + 64 * 72;
    float* sS = reinterpret_cast<float*>(sVl + 64 * 72);            // 128x68
    __nv_bfloat16* sPh = reinterpret_cast<__nv_bfloat16*>(sS + 128 * 68); // 128x72
    __nv_bfloat16* sPl = sPh + 128 * 72;
    float* sAlpha = reinterpret_cast<float*>(sPl + 128 * 72);       // 128

    const int qt = blockIdx.x;      // 0..7
    const int bh = blockIdx.y;      // 0..63
    const int tid = threadIdx.x;
    const int wid = tid >> 5, lane = tid & 31;
    const int g = lane >> 2, t = lane & 3;
    const int warpM = wid >> 1;     // 0..3
    const int warpN = wid & 1;      // 0..1
    const int srow = tid >> 1;      // softmax row 0..127
    const int shalf = tid & 1;      // half-row 0/1
    const float scale = __expf(temp[0]);

    // load Q tile (128x64) hi/lo
    const size_t qbase = ((size_t)bh * 1024 + qt * 128) * 64;
#pragma unroll
    for (int it = 0; it < 4; it++) {
        int i = tid + it * 256;     // float4 units
        int row = i >> 3, c = (i & 7) * 8;
        *reinterpret_cast<float4*>(&sQh[row * 72 + c]) =
            *reinterpret_cast<const float4*>(&g_qh[qbase + row * 64 + c]);
        *reinterpret_cast<float4*>(&sQl[row * 72 + c]) =
            *reinterpret_cast<const float4*>(&g_ql[qbase + row * 64 + c]);
    }

    float oacc[2][4][4];
#pragma unroll
    for (int a = 0; a < 2; a++)
#pragma unroll
        for (int b = 0; b < 4; b++)
#pragma unroll
            for (int c = 0; c < 4; c++) oacc[a][b][c] = 0.f;
    float m_i = -1e30f, l_i = 0.f;

    __syncthreads();

    for (int kt = 0; kt < 16; kt++) {
        // ---- load K tile (64x64) and V^T tile (64 d x 64 key), hi/lo ----
        const size_t kbase = ((size_t)bh * 1024 + kt * 64) * 64;
        const size_t vbase = ((size_t)bh * 64) * 1024 + kt * 64;
#pragma unroll
        for (int it = 0; it < 2; it++) {
            int i = tid + it * 256;
            int row = i >> 3, c = (i & 7) * 8;
            *reinterpret_cast<float4*>(&sKh[row * 72 + c]) =
                *reinterpret_cast<const float4*>(&g_kh[kbase + (size_t)row * 64 + c]);
            *reinterpret_cast<float4*>(&sKl[row * 72 + c]) =
                *reinterpret_cast<const float4*>(&g_kl[kbase + (size_t)row * 64 + c]);
            *reinterpret_cast<float4*>(&sVh[row * 72 + c]) =
                *reinterpret_cast<const float4*>(&g_vth[vbase + (size_t)row * 1024 + c]);
            *reinterpret_cast<float4*>(&sVl[row * 72 + c]) =
                *reinterpret_cast<const float4*>(&g_vtl[vbase + (size_t)row * 1024 + c]);
        }
        __syncthreads();

        // ---- S = Q K^T (split: QhKh + QhKl + QlKh) ----
        float sacc[2][4][4];
#pragma unroll
        for (int a = 0; a < 2; a++)
#pragma unroll
            for (int b = 0; b < 4; b++)
#pragma unroll
                for (int c = 0; c < 4; c++) sacc[a][b][c] = 0.f;
#pragma unroll
        for (int kk = 0; kk < 64; kk += 16) {
            unsigned ah[2][4], al[2][4], bhf[4][2], blf[4][2];
#pragma unroll
            for (int tm = 0; tm < 2; tm++) {
                int r = warpM * 32 + tm * 16 + g;
                const __nv_bfloat16* p = &sQh[r * 72 + kk + 2 * t];
                const __nv_bfloat16* q = &sQl[r * 72 + kk + 2 * t];
                ah[tm][0] = *reinterpret_cast<const unsigned*>(p);
                ah[tm][1] = *reinterpret_cast<const unsigned*>(p + 8 * 72);
                ah[tm][2] = *reinterpret_cast<const unsigned*>(p + 8);
                ah[tm][3] = *reinterpret_cast<const unsigned*>(p + 8 * 72 + 8);
                al[tm][0] = *reinterpret_cast<const unsigned*>(q);
                al[tm][1] = *reinterpret_cast<const unsigned*>(q + 8 * 72);
                al[tm][2] = *reinterpret_cast<const unsigned*>(q + 8);
                al[tm][3] = *reinterpret_cast<const unsigned*>(q + 8 * 72 + 8);
            }
#pragma unroll
            for (int tn = 0; tn < 4; tn++) {
                int n = warpN * 32 + tn * 8 + g;
                const __nv_bfloat16* p = &sKh[n * 72 + kk + 2 * t];
                const __nv_bfloat16* q = &sKl[n * 72 + kk + 2 * t];
                bhf[tn][0] = *reinterpret_cast<const unsigned*>(p);
                bhf[tn][1] = *reinterpret_cast<const unsigned*>(p + 8);
                blf[tn][0] = *reinterpret_cast<const unsigned*>(q);
                blf[tn][1] = *reinterpret_cast<const unsigned*>(q + 8);
            }
#pragma unroll
            for (int tm = 0; tm < 2; tm++)
#pragma unroll
                for (int tn = 0; tn < 4; tn++) {
                    MMA16816(sacc[tm][tn], ah[tm], bhf[tn]);
                    MMA16816(sacc[tm][tn], ah[tm], blf[tn]);
                    MMA16816(sacc[tm][tn], al[tm], bhf[tn]);
                }
        }
        // store S to smem (fp32)
#pragma unroll
        for (int tm = 0; tm < 2; tm++)
#pragma unroll
            for (int tn = 0; tn < 4; tn++) {
                int r = warpM * 32 + tm * 16 + g;
                int n0 = warpN * 32 + tn * 8 + 2 * t;
                float2 v0 = {sacc[tm][tn][0], sacc[tm][tn][1]};
                float2 v1 = {sacc[tm][tn][2], sacc[tm][tn][3]};
                *reinterpret_cast<float2*>(&sS[r * 68 + n0]) = v0;
                *reinterpret_cast<float2*>(&sS[(r + 8) * 68 + n0]) = v1;
            }
        __syncthreads();

        // ---- online softmax: 2 threads per row, 32 cols each ----
        {
            const int cbase = shalf * 32;
            float sv[32];
#pragma unroll
            for (int c4 = 0; c4 < 8; c4++) {
                float4 v = *reinterpret_cast<float4*>(&sS[srow * 68 + cbase + c4 * 4]);
                sv[c4 * 4 + 0] = v.x * scale;
                sv[c4 * 4 + 1] = v.y * scale;
                sv[c4 * 4 + 2] = v.z * scale;
                sv[c4 * 4 + 3] = v.w * scale;
            }
            int qg = qt * 128 + srow;
            int cd = qg - kt * 64;            // diagonal col within tile
            if (cd >= cbase && cd < cbase + 32) sv[cd - cbase] = -1e30f;
            float tmax = sv[0];
#pragma unroll
            for (int c = 1; c < 32; c++) tmax = fmaxf(tmax, sv[c]);
            tmax = fmaxf(tmax, __shfl_xor_sync(0xffffffffu, tmax, 1));
            float mn = fmaxf(m_i, tmax);
            float alpha = __expf(m_i - mn);
            m_i = mn;
            float rs = 0.f;
#pragma unroll
            for (int c = 0; c < 32; c += 2) {
                float p0 = __expf(sv[c] - mn);
                float p1 = __expf(sv[c + 1] - mn);
                rs += p0 + p1;
                __nv_bfloat16 h0 = __float2bfloat16(p0);
                __nv_bfloat16 h1 = __float2bfloat16(p1);
                __nv_bfloat16 e0 = __float2bfloat16(p0 - __bfloat162float(h0));
                __nv_bfloat16 e1 = __float2bfloat16(p1 - __bfloat162float(h1));
                *reinterpret_cast<__nv_bfloat162*>(&sPh[srow * 72 + cbase + c]) = {h0, h1};
                *reinterpret_cast<__nv_bfloat162*>(&sPl[srow * 72 + cbase + c]) = {e0, e1};
            }
            rs += __shfl_xor_sync(0xffffffffu, rs, 1);
            l_i = l_i * alpha + rs;
            if (shalf == 0) sAlpha[srow] = alpha;
        }
        __syncthreads();

        // ---- O = O*alpha + P V  (split: PhVh + PhVl + PlVh) ----
#pragma unroll
        for (int tm = 0; tm < 2; tm++) {
            int r = warpM * 32 + tm * 16 + g;
            float a0 = sAlpha[r], a1 = sAlpha[r + 8];
#pragma unroll
            for (int tn = 0; tn < 4; tn++) {
                oacc[tm][tn][0] *= a0;
                oacc[tm][tn][1] *= a0;
                oacc[tm][tn][2] *= a1;
                oacc[tm][tn][3] *= a1;
            }
        }
#pragma unroll
        for (int kk = 0; kk < 64; kk += 16) {
            unsigned ph[2][4], pl[2][4], vhf[4][2], vlf[4][2];
#pragma unroll
            for (int tm = 0; tm < 2; tm++) {
                int r = warpM * 32 + tm * 16 + g;
                const __nv_bfloat16* p = &sPh[r * 72 + kk + 2 * t];
                const __nv_bfloat16* q = &sPl[r * 72 + kk + 2 * t];
                ph[tm][0] = *reinterpret_cast<const unsigned*>(p);
                ph[tm][1] = *reinterpret_cast<const unsigned*>(p + 8 * 72);
                ph[tm][2] = *reinterpret_cast<const unsigned*>(p + 8);
                ph[tm][3] = *reinterpret_cast<const unsigned*>(p + 8 * 72 + 8);
                pl[tm][0] = *reinterpret_cast<const unsigned*>(q);
                pl[tm][1] = *reinterpret_cast<const unsigned*>(q + 8 * 72);
                pl[tm][2] = *reinterpret_cast<const unsigned*>(q + 8);
                pl[tm][3] = *reinterpret_cast<const unsigned*>(q + 8 * 72 + 8);
            }
#pragma unroll
            for (int tn = 0; tn < 4; tn++) {
                int n = warpN * 32 + tn * 8 + g;   // d index
                const __nv_bfloat16* p = &sVh[n * 72 + kk + 2 * t];
                const __nv_bfloat16* q = &sVl[n * 72 + kk + 2 * t];
                vhf[tn][0] = *reinterpret_cast<const unsigned*>(p);
                vhf[tn][1] = *reinterpret_cast<const unsigned*>(p + 8);
                vlf[tn][0] = *reinterpret_cast<const unsigned*>(q);
                vlf[tn][1] = *reinterpret_cast<const unsigned*>(q + 8);
            }
#pragma unroll
            for (int tm = 0; tm < 2; tm++)
#pragma unroll
                for (int tn = 0; tn < 4; tn++) {
                    MMA16816(oacc[tm][tn], ph[tm], vhf[tn]);
                    MMA16816(oacc[tm][tn], ph[tm], vlf[tn]);
                    MMA16816(oacc[tm][tn], pl[tm], vhf[tn]);
                }
        }
        __syncthreads();
    }

    // ---- normalize and write split bf16 attention output ----
    if (shalf == 0) sAlpha[srow] = 1.f / l_i;
    __syncthreads();

    const int b = bh >> 3, h = bh & 7;
#pragma unroll
    for (int tm = 0; tm < 2; tm++) {
        int r = warpM * 32 + tm * 16 + g;
        float i0 = sAlpha[r], i1 = sAlpha[r + 8];
        int qg0 = qt * 128 + r;
#pragma unroll
        for (int tn = 0; tn < 4; tn++) {
            int d = warpN * 32 + tn * 8 + 2 * t;
            float o00 = oacc[tm][tn][0] * i0, o01 = oacc[tm][tn][1] * i0;
            float o10 = oacc[tm][tn][2] * i1, o11 = oacc[tm][tn][3] * i1;
            __nv_bfloat16 h00 = __float2bfloat16(o00);
            __nv_bfloat16 h01 = __float2bfloat16(o01);
            __nv_bfloat16 h10 = __float2bfloat16(o10);
            __nv_bfloat16 h11 = __float2bfloat16(o11);
            size_t p0 = ((size_t)(b * 1024 + qg0)) * 512 + h * 64 + d;
            size_t p1 = ((size_t)(b * 1024 + qg0 + 8)) * 512 + h * 64 + d;
            *reinterpret_cast<__nv_bfloat162*>(&g_aoh[p0]) = {h00, h01};
            *reinterpret_cast<__nv_bfloat162*>(&g_aoh[p1]) = {h10, h11};
            *reinterpret_cast<__nv_bfloat162*>(&g_aol[p0]) = {
                __float2bfloat16(o00 - __bfloat162float(h00)),
                __float2bfloat16(o01 - __bfloat162float(h01))};
            *reinterpret_cast<__nv_bfloat162*>(&g_aol[p1]) = {
                __float2bfloat16(o10 - __bfloat162float(h10)),
                __float2bfloat16(o11 - __bfloat162float(h11))};
        }
    }
}

// ---------------------------------------------------------------------------
extern "C" void kernel_launch(void* const* d_in, const int* in_sizes, int n_in,
                              void* d_out, int out_size)
{
    const float* x      = (const float*)d_in[0];   // (8,1024,512)
    const float* w_qkv  = (const float*)d_in[1];   // (512,1536)
    const float* temp   = (const float*)d_in[2];   // scalar
    const float* w_out  = (const float*)d_in[3];   // (512,512)
    const float* b_out  = (const float*)d_in[4];   // (512)
    float* out = (float*)d_out;                    // (8,1024,512)

    cudaFuncSetAttribute(attn_kernel,
                         cudaFuncAttributeMaxDynamicSharedMemorySize, ATTN_SMEM);
    cudaFuncSetAttribute(gemm_qkv_kernel,
                         cudaFuncAttributeMaxDynamicSharedMemorySize, GEMM_SMEM);
    cudaFuncSetAttribute(gemm_out_kernel,
                         cudaFuncAttributeMaxDynamicSharedMemorySize, GEMM_SMEM);

    split_x_kernel<<<4096, 256>>>(x);
    split_wT_kernel<<<dim3(48, 16), 256>>>(w_qkv, 1536, 0);
    split_wT_kernel<<<dim3(16, 16), 256>>>(w_out, 512, 1);
    gemm_qkv_kernel<<<dim3(12, 64), 256, GEMM_SMEM>>>();
    attn_kernel<<<dim3(8, 64), 256, ATTN_SMEM>>>(temp);
    gemm_out_kernel<<<dim3(4, 64), 256, GEMM_SMEM>>>(b_out, out);
}

// round 17
// speedup vs baseline: 3.3721x; 1.0036x over previous
#include <cuda_runtime.h>
#include <cuda_bf16.h>
#include <math.h>

// Problem constants: B=8, N=1024, DIM=512, HEADS=8, DIM_HEAD=64, INNER=512
// M = B*N = 8192

// -------------------- device scratch (no allocation) -----------------------
__device__ __nv_bfloat16 g_xh[8192 * 512];   // x split hi/lo
__device__ __nv_bfloat16 g_xl[8192 * 512];
__device__ __nv_bfloat16 g_w1h[1536 * 512];  // w_qkv^T split (K-major: [n][k])
__device__ __nv_bfloat16 g_w1l[1536 * 512];
__device__ __nv_bfloat16 g_w2h[512 * 512];   // w_out^T split
__device__ __nv_bfloat16 g_w2l[512 * 512];
__device__ __nv_bfloat16 g_aoh[8192 * 512];  // attention output split hi/lo
__device__ __nv_bfloat16 g_aol[8192 * 512];

__device__ __nv_bfloat16 g_qh[64 * 1024 * 64];  // (bh, n, d) bf16 hi/lo
__device__ __nv_bfloat16 g_ql[64 * 1024 * 64];
__device__ __nv_bfloat16 g_kh[64 * 1024 * 64];
__device__ __nv_bfloat16 g_kl[64 * 1024 * 64];
__device__ __nv_bfloat16 g_vth[64 * 64 * 1024]; // (bh, d, n)  V transposed
__device__ __nv_bfloat16 g_vtl[64 * 64 * 1024];

// -------------------- mma.sync helper --------------------------------------
#define MMA16816(c, a, b)                                                     \
    asm volatile(                                                             \
        "mma.sync.aligned.m16n8k16.row.col.f32.bf16.bf16.f32 "                \
        "{%0,%1,%2,%3}, {%4,%5,%6,%7}, {%8,%9}, {%0,%1,%2,%3};"               \
        : "+f"((c)[0]), "+f"((c)[1]), "+f"((c)[2]), "+f"((c)[3])              \
        : "r"((a)[0]), "r"((a)[1]), "r"((a)[2]), "r"((a)[3]),                 \
          "r"((b)[0]), "r"((b)[1]))

__device__ __forceinline__ void cp_async16(void* sdst, const void* gsrc)
{
    unsigned s = (unsigned)__cvta_generic_to_shared(sdst);
    asm volatile("cp.async.cg.shared.global [%0], [%1], 16;\n" :: "r"(s), "l"(gsrc));
}
#define CP_COMMIT() asm volatile("cp.async.commit_group;\n" ::: "memory")
#define CP_WAIT0()  asm volatile("cp.async.wait_group 0;\n" ::: "memory")

// -------------------- prep: split x into bf16 hi/lo -------------------------
__global__ __launch_bounds__(256) void split_x_kernel(const float* __restrict__ X)
{
    int i = blockIdx.x * 256 + threadIdx.x;   // 4 elems per thread
    float4 v = *reinterpret_cast<const float4*>(X + (size_t)i * 4);
    float e[4] = {v.x, v.y, v.z, v.w};
#pragma unroll
    for (int j = 0; j < 4; j++) {
        __nv_bfloat16 h = __float2bfloat16(e[j]);
        g_xh[(size_t)i * 4 + j] = h;
        g_xl[(size_t)i * 4 + j] = __float2bfloat16(e[j] - __bfloat162float(h));
    }
}

// -------------------- prep: transpose + split weights -----------------------
__global__ __launch_bounds__(256) void split_wT_kernel(const float* __restrict__ W,
                                                       int ncols, int which)
{
    __shared__ float tile[32][33];
    __nv_bfloat16* Th = which ? g_w2h : g_w1h;
    __nv_bfloat16* Tl = which ? g_w2l : g_w1l;
    const int no = blockIdx.x * 32;
    const int ko = blockIdx.y * 32;
    const int tx = threadIdx.x & 31;
    const int ty = threadIdx.x >> 5;
#pragma unroll
    for (int j = 0; j < 32; j += 8)
        tile[ty + j][tx] = W[(size_t)(ko + ty + j) * ncols + no + tx];
    __syncthreads();
#pragma unroll
    for (int j = 0; j < 32; j += 8) {
        int n = no + ty + j, k = ko + tx;
        float v = tile[tx][ty + j];
        __nv_bfloat16 h = __float2bfloat16(v);
        Th[(size_t)n * 512 + k] = h;
        Tl[(size_t)n * 512 + k] = __float2bfloat16(v - __bfloat162float(h));
    }
}

// -------------------- tensor-core GEMM mainloop (double-buffered) -----------
// 128x128 CTA tile, K=512, 8 warps (2 m x 4 n), warp tile 64x32.
// 2-stage cp.async pipeline: wait(i) -> sync -> issue(i+1) -> compute(i).
// Split terms issued TERM-MAJOR to break per-accumulator RAW chains.
#define GSTAGE (4 * 128 * 40)           // elems per stage
#define GEMM_SMEM (2 * GSTAGE * 2)      // bytes = 81920

__device__ __forceinline__ void gemm_issue_tile(
    const __nv_bfloat16* __restrict__ Ah, const __nv_bfloat16* __restrict__ Al,
    const __nv_bfloat16* __restrict__ Bh, const __nv_bfloat16* __restrict__ Bl,
    int bm, int bn, int kc, __nv_bfloat16* base)
{
    const int tid = threadIdx.x;
#pragma unroll
    for (int it = 0; it < 2; it++) {
        int i = tid + it * 256;
        int row = i >> 2, seg = i & 3;
        int sidx = row * 40 + seg * 8;
        size_t ga = (size_t)(bm + row) * 512 + kc + seg * 8;
        size_t gb = (size_t)(bn + row) * 512 + kc + seg * 8;
        cp_async16(base + sidx,                Ah + ga);
        cp_async16(base + 128 * 40 + sidx,     Al + ga);
        cp_async16(base + 2 * 128 * 40 + sidx, Bh + gb);
        cp_async16(base + 3 * 128 * 40 + sidx, Bl + gb);
    }
    CP_COMMIT();
}

__device__ __forceinline__ void gemm_mainloop_bf16(
    const __nv_bfloat16* __restrict__ Ah, const __nv_bfloat16* __restrict__ Al,
    const __nv_bfloat16* __restrict__ Bh, const __nv_bfloat16* __restrict__ Bl,
    int bm, int bn, __nv_bfloat16* sm, float acc[4][4][4])
{
    const int tid = threadIdx.x;
    const int wid = tid >> 5;
    const int lane = tid & 31;
    const int warpM = wid >> 2;
    const int warpN = wid & 3;
    const int g = lane >> 2;
    const int t = lane & 3;

    gemm_issue_tile(Ah, Al, Bh, Bl, bm, bn, 0, sm);

    for (int kc = 0; kc < 512; kc += 32) {
        const int st = (kc >> 5) & 1;
        CP_WAIT0();
        __syncthreads();
        if (kc + 32 < 512)
            gemm_issue_tile(Ah, Al, Bh, Bl, bm, bn, kc + 32, sm + (st ^ 1) * GSTAGE);

        __nv_bfloat16* sAh = sm + st * GSTAGE;
        __nv_bfloat16* sAl = sAh + 128 * 40;
        __nv_bfloat16* sBh = sAl + 128 * 40;
        __nv_bfloat16* sBl = sBh + 128 * 40;
#pragma unroll
        for (int kk = 0; kk < 32; kk += 16) {
            unsigned ah[4][4], al[4][4], bh[4][2], bl[4][2];
#pragma unroll
            for (int tm = 0; tm < 4; tm++) {
                int r = warpM * 64 + tm * 16 + g;
                const __nv_bfloat16* p = &sAh[r * 40 + kk + 2 * t];
                const __nv_bfloat16* q = &sAl[r * 40 + kk + 2 * t];
                ah[tm][0] = *reinterpret_cast<const unsigned*>(p);
                ah[tm][1] = *reinterpret_cast<const unsigned*>(p + 8 * 40);
                ah[tm][2] = *reinterpret_cast<const unsigned*>(p + 8);
                ah[tm][3] = *reinterpret_cast<const unsigned*>(p + 8 * 40 + 8);
                al[tm][0] = *reinterpret_cast<const unsigned*>(q);
                al[tm][1] = *reinterpret_cast<const unsigned*>(q + 8 * 40);
                al[tm][2] = *reinterpret_cast<const unsigned*>(q + 8);
                al[tm][3] = *reinterpret_cast<const unsigned*>(q + 8 * 40 + 8);
            }
#pragma unroll
            for (int tn = 0; tn < 4; tn++) {
                int n = warpN * 32 + tn * 8 + g;
                const __nv_bfloat16* p = &sBh[n * 40 + kk + 2 * t];
                const __nv_bfloat16* q = &sBl[n * 40 + kk + 2 * t];
                bh[tn][0] = *reinterpret_cast<const unsigned*>(p);
                bh[tn][1] = *reinterpret_cast<const unsigned*>(p + 8);
                bl[tn][0] = *reinterpret_cast<const unsigned*>(q);
                bl[tn][1] = *reinterpret_cast<const unsigned*>(q + 8);
            }
            // term-major: 16-MMA spacing between writes to the same accumulator
#pragma unroll
            for (int tm = 0; tm < 4; tm++)
#pragma unroll
                for (int tn = 0; tn < 4; tn++)
                    MMA16816(acc[tm][tn], ah[tm], bh[tn]);
#pragma unroll
            for (int tm = 0; tm < 4; tm++)
#pragma unroll
                for (int tn = 0; tn < 4; tn++)
                    MMA16816(acc[tm][tn], ah[tm], bl[tn]);
#pragma unroll
            for (int tm = 0; tm < 4; tm++)
#pragma unroll
                for (int tn = 0; tn < 4; tn++)
                    MMA16816(acc[tm][tn], al[tm], bh[tn]);
        }
        __syncthreads();
    }
}

// -------------------- GEMM1: qkv -> bf16 q/k + transposed v -----------------
__global__ __launch_bounds__(256) void gemm_qkv_kernel()
{
    extern __shared__ __align__(16) __nv_bfloat16 smg[];
    const int bm = blockIdx.y * 128;
    const int bn = blockIdx.x * 128;

    float acc[4][4][4];
#pragma unroll
    for (int a = 0; a < 4; a++)
#pragma unroll
        for (int b = 0; b < 4; b++)
#pragma unroll
            for (int c = 0; c < 4; c++) acc[a][b][c] = 0.f;

    gemm_mainloop_bf16(g_xh, g_xl, g_w1h, g_w1l, bm, bn, smg, acc);

    const int wid = threadIdx.x >> 5, lane = threadIdx.x & 31;
    const int warpM = wid >> 2, warpN = wid & 3;
    const int g = lane >> 2, t = lane & 3;
#pragma unroll
    for (int tm = 0; tm < 4; tm++)
#pragma unroll
        for (int tn = 0; tn < 4; tn++) {
            int m0 = bm + warpM * 64 + tm * 16 + g;
            int col0 = bn + warpN * 32 + tn * 8 + 2 * t;
            int which = col0 >> 9;
            int h = (col0 & 511) >> 6;
            int d = col0 & 63;
            int b0 = m0 >> 10, n0 = m0 & 1023;
            int bh0 = (b0 << 3) + h;
            float v00 = acc[tm][tn][0], v01 = acc[tm][tn][1];
            float v10 = acc[tm][tn][2], v11 = acc[tm][tn][3];
            __nv_bfloat16 h00 = __float2bfloat16(v00);
            __nv_bfloat16 h01 = __float2bfloat16(v01);
            __nv_bfloat16 h10 = __float2bfloat16(v10);
            __nv_bfloat16 h11 = __float2bfloat16(v11);
            __nv_bfloat16 l00 = __float2bfloat16(v00 - __bfloat162float(h00));
            __nv_bfloat16 l01 = __float2bfloat16(v01 - __bfloat162float(h01));
            __nv_bfloat16 l10 = __float2bfloat16(v10 - __bfloat162float(h10));
            __nv_bfloat16 l11 = __float2bfloat16(v11 - __bfloat162float(h11));
            if (which < 2) {
                __nv_bfloat16* dh = which ? g_kh : g_qh;
                __nv_bfloat16* dl = which ? g_kl : g_ql;
                size_t r0 = ((size_t)(bh0 * 1024 + n0)) * 64 + d;
                size_t r1 = ((size_t)(bh0 * 1024 + n0 + 8)) * 64 + d;
                *reinterpret_cast<__nv_bfloat162*>(dh + r0) = {h00, h01};
                *reinterpret_cast<__nv_bfloat162*>(dl + r0) = {l00, l01};
                *reinterpret_cast<__nv_bfloat162*>(dh + r1) = {h10, h11};
                *reinterpret_cast<__nv_bfloat162*>(dl + r1) = {l10, l11};
            } else {
                // V transposed: (bh, d, n)
                size_t c0 = ((size_t)(bh0 * 64 + d)) * 1024 + n0;
                size_t c1 = ((size_t)(bh0 * 64 + d + 1)) * 1024 + n0;
                g_vth[c0] = h00;     g_vtl[c0] = l00;
                g_vth[c1] = h01;     g_vtl[c1] = l01;
                g_vth[c0 + 8] = h10; g_vtl[c0 + 8] = l10;
                g_vth[c1 + 8] = h11; g_vtl[c1 + 8] = l11;
            }
        }
}

// -------------------- GEMM2: out projection + bias --------------------------
__global__ __launch_bounds__(256) void gemm_out_kernel(
    const float* __restrict__ bias, float* __restrict__ C)
{
    extern __shared__ __align__(16) __nv_bfloat16 smg[];
    const int bm = blockIdx.y * 128;
    const int bn = blockIdx.x * 128;

    float acc[4][4][4];
#pragma unroll
    for (int a = 0; a < 4; a++)
#pragma unroll
        for (int b = 0; b < 4; b++)
#pragma unroll
            for (int c = 0; c < 4; c++) acc[a][b][c] = 0.f;

    gemm_mainloop_bf16(g_aoh, g_aol, g_w2h, g_w2l, bm, bn, smg, acc);

    const int wid = threadIdx.x >> 5, lane = threadIdx.x & 31;
    const int warpM = wid >> 2, warpN = wid & 3;
    const int g = lane >> 2, t = lane & 3;
#pragma unroll
    for (int tm = 0; tm < 4; tm++)
#pragma unroll
        for (int tn = 0; tn < 4; tn++) {
            int m0 = bm + warpM * 64 + tm * 16 + g;
            int col0 = bn + warpN * 32 + tn * 8 + 2 * t;
            float b0v = bias[col0], b1v = bias[col0 + 1];
            float2 v0 = {acc[tm][tn][0] + b0v, acc[tm][tn][1] + b1v};
            float2 v1 = {acc[tm][tn][2] + b0v, acc[tm][tn][3] + b1v};
            *reinterpret_cast<float2*>(C + (size_t)m0 * 512 + col0) = v0;
            *reinterpret_cast<float2*>(C + (size_t)(m0 + 8) * 512 + col0) = v1;
        }
}

// -------------------- tensor-core flash attention ---------------------------
// One CTA per (bh, 128-query tile). 8 warps: warpM=wid>>1 (4 x 32 rows),
// warpN=wid&1 (2 x 32 cols). 64-key tiles, online softmax, split-bf16 MMA.
// Split terms issued TERM-MAJOR (same per-accumulator order: hh, hl, lh).
#define ATTN_SMEM 145920
__global__ __launch_bounds__(256) void attn_kernel(const float* __restrict__ temp)
{
    extern __shared__ char smraw[];
    __nv_bfloat16* sQh = reinterpret_cast<__nv_bfloat16*>(smraw);   // 128x72
    __nv_bfloat16* sQl = sQh + 128 * 72;
    __nv_bfloat16* sKh = sQl + 128 * 72;                            // 64x72
    __nv_bfloat16* sKl = sKh + 64 * 72;
    __nv_bfloat16* sVh = sKl + 64 * 72;                             // 64x72 (d, key)
    __nv_bfloat16* sVl = sVh + 64 * 72;
    float* sS = reinterpret_cast<float*>(sVl + 64 * 72);            // 128x68
    __nv_bfloat16* sPh = reinterpret_cast<__nv_bfloat16*>(sS + 128 * 68); // 128x72
    __nv_bfloat16* sPl = sPh + 128 * 72;
    float* sAlpha = reinterpret_cast<float*>(sPl + 128 * 72);       // 128

    const int qt = blockIdx.x;      // 0..7
    const int bh = blockIdx.y;      // 0..63
    const int tid = threadIdx.x;
    const int wid = tid >> 5, lane = tid & 31;
    const int g = lane >> 2, t = lane & 3;
    const int warpM = wid >> 1;     // 0..3
    const int warpN = wid & 1;      // 0..1
    const int srow = tid >> 1;      // softmax row 0..127
    const int shalf = tid & 1;      // half-row 0/1
    const float scale = __expf(temp[0]);

    const size_t qbase = ((size_t)bh * 1024 + qt * 128) * 64;
#pragma unroll
    for (int it = 0; it < 4; it++) {
        int i = tid + it * 256;
        int row = i >> 3, c = (i & 7) * 8;
        *reinterpret_cast<float4*>(&sQh[row * 72 + c]) =
            *reinterpret_cast<const float4*>(&g_qh[qbase + row * 64 + c]);
        *reinterpret_cast<float4*>(&sQl[row * 72 + c]) =
            *reinterpret_cast<const float4*>(&g_ql[qbase + row * 64 + c]);
    }

    float oacc[2][4][4];
#pragma unroll
    for (int a = 0; a < 2; a++)
#pragma unroll
        for (int b = 0; b < 4; b++)
#pragma unroll
            for (int c = 0; c < 4; c++) oacc[a][b][c] = 0.f;
    float m_i = -1e30f, l_i = 0.f;

    __syncthreads();

    for (int kt = 0; kt < 16; kt++) {
        const size_t kbase = ((size_t)bh * 1024 + kt * 64) * 64;
        const size_t vbase = ((size_t)bh * 64) * 1024 + kt * 64;
#pragma unroll
        for (int it = 0; it < 2; it++) {
            int i = tid + it * 256;
            int row = i >> 3, c = (i & 7) * 8;
            *reinterpret_cast<float4*>(&sKh[row * 72 + c]) =
                *reinterpret_cast<const float4*>(&g_kh[kbase + (size_t)row * 64 + c]);
            *reinterpret_cast<float4*>(&sKl[row * 72 + c]) =
                *reinterpret_cast<const float4*>(&g_kl[kbase + (size_t)row * 64 + c]);
            *reinterpret_cast<float4*>(&sVh[row * 72 + c]) =
                *reinterpret_cast<const float4*>(&g_vth[vbase + (size_t)row * 1024 + c]);
            *reinterpret_cast<float4*>(&sVl[row * 72 + c]) =
                *reinterpret_cast<const float4*>(&g_vtl[vbase + (size_t)row * 1024 + c]);
        }
        __syncthreads();

        float sacc[2][4][4];
#pragma unroll
        for (int a = 0; a < 2; a++)
#pragma unroll
            for (int b = 0; b < 4; b++)
#pragma unroll
                for (int c = 0; c < 4; c++) sacc[a][b][c] = 0.f;
#pragma unroll
        for (int kk = 0; kk < 64; kk += 16) {
            unsigned ah[2][4], al[2][4], bhf[4][2], blf[4][2];
#pragma unroll
            for (int tm = 0; tm < 2; tm++) {
                int r = warpM * 32 + tm * 16 + g;
                const __nv_bfloat16* p = &sQh[r * 72 + kk + 2 * t];
                const __nv_bfloat16* q = &sQl[r * 72 + kk + 2 * t];
                ah[tm][0] = *reinterpret_cast<const unsigned*>(p);
                ah[tm][1] = *reinterpret_cast<const unsigned*>(p + 8 * 72);
                ah[tm][2] = *reinterpret_cast<const unsigned*>(p + 8);
                ah[tm][3] = *reinterpret_cast<const unsigned*>(p + 8 * 72 + 8);
                al[tm][0] = *reinterpret_cast<const unsigned*>(q);
                al[tm][1] = *reinterpret_cast<const unsigned*>(q + 8 * 72);
                al[tm][2] = *reinterpret_cast<const unsigned*>(q + 8);
                al[tm][3] = *reinterpret_cast<const unsigned*>(q + 8 * 72 + 8);
            }
#pragma unroll
            for (int tn = 0; tn < 4; tn++) {
                int n = warpN * 32 + tn * 8 + g;
                const __nv_bfloat16* p = &sKh[n * 72 + kk + 2 * t];
                const __nv_bfloat16* q = &sKl[n * 72 + kk + 2 * t];
                bhf[tn][0] = *reinterpret_cast<const unsigned*>(p);
                bhf[tn][1] = *reinterpret_cast<const unsigned*>(p + 8);
                blf[tn][0] = *reinterpret_cast<const unsigned*>(q);
                blf[tn][1] = *reinterpret_cast<const unsigned*>(q + 8);
            }
            // term-major ordering
#pragma unroll
            for (int tm = 0; tm < 2; tm++)
#pragma unroll
                for (int tn = 0; tn < 4; tn++)
                    MMA16816(sacc[tm][tn], ah[tm], bhf[tn]);
#pragma unroll
            for (int tm = 0; tm < 2; tm++)
#pragma unroll
                for (int tn = 0; tn < 4; tn++)
                    MMA16816(sacc[tm][tn], ah[tm], blf[tn]);
#pragma unroll
            for (int tm = 0; tm < 2; tm++)
#pragma unroll
                for (int tn = 0; tn < 4; tn++)
                    MMA16816(sacc[tm][tn], al[tm], bhf[tn]);
        }
#pragma unroll
        for (int tm = 0; tm < 2; tm++)
#pragma unroll
            for (int tn = 0; tn < 4; tn++) {
                int r = warpM * 32 + tm * 16 + g;
                int n0 = warpN * 32 + tn * 8 + 2 * t;
                float2 v0 = {sacc[tm][tn][0], sacc[tm][tn][1]};
                float2 v1 = {sacc[tm][tn][2], sacc[tm][tn][3]};
                *reinterpret_cast<float2*>(&sS[r * 68 + n0]) = v0;
                *reinterpret_cast<float2*>(&sS[(r + 8) * 68 + n0]) = v1;
            }
        __syncthreads();

        {
            const int cbase = shalf * 32;
            float sv[32];
#pragma unroll
            for (int c4 = 0; c4 < 8; c4++) {
                float4 v = *reinterpret_cast<float4*>(&sS[srow * 68 + cbase + c4 * 4]);
                sv[c4 * 4 + 0] = v.x * scale;
                sv[c4 * 4 + 1] = v.y * scale;
                sv[c4 * 4 + 2] = v.z * scale;
                sv[c4 * 4 + 3] = v.w * scale;
            }
            int qg = qt * 128 + srow;
            int cd = qg - kt * 64;            // diagonal col within tile
            if (cd >= cbase && cd < cbase + 32) sv[cd - cbase] = -1e30f;
            float tmax = sv[0];
#pragma unroll
            for (int c = 1; c < 32; c++) tmax = fmaxf(tmax, sv[c]);
            tmax = fmaxf(tmax, __shfl_xor_sync(0xffffffffu, tmax, 1));
            float mn = fmaxf(m_i, tmax);
            float alpha = __expf(m_i - mn);
            m_i = mn;
            float rs = 0.f;
#pragma unroll
            for (int c = 0; c < 32; c += 2) {
                float p0 = __expf(sv[c] - mn);
                float p1 = __expf(sv[c + 1] - mn);
                rs += p0 + p1;
                __nv_bfloat16 h0 = __float2bfloat16(p0);
                __nv_bfloat16 h1 = __float2bfloat16(p1);
                __nv_bfloat16 e0 = __float2bfloat16(p0 - __bfloat162float(h0));
                __nv_bfloat16 e1 = __float2bfloat16(p1 - __bfloat162float(h1));
                *reinterpret_cast<__nv_bfloat162*>(&sPh[srow * 72 + cbase + c]) = {h0, h1};
                *reinterpret_cast<__nv_bfloat162*>(&sPl[srow * 72 + cbase + c]) = {e0, e1};
            }
            rs += __shfl_xor_sync(0xffffffffu, rs, 1);
            l_i = l_i * alpha + rs;
            if (shalf == 0) sAlpha[srow] = alpha;
        }
        __syncthreads();

#pragma unroll
        for (int tm = 0; tm < 2; tm++) {
            int r = warpM * 32 + tm * 16 + g;
            float a0 = sAlpha[r], a1 = sAlpha[r + 8];
#pragma unroll
            for (int tn = 0; tn < 4; tn++) {
                oacc[tm][tn][0] *= a0;
                oacc[tm][tn][1] *= a0;
                oacc[tm][tn][2] *= a1;
                oacc[tm][tn][3] *= a1;
            }
        }
#pragma unroll
        for (int kk = 0; kk < 64; kk += 16) {
            unsigned ph[2][4], pl[2][4], vhf[4][2], vlf[4][2];
#pragma unroll
            for (int tm = 0; tm < 2; tm++) {
                int r = warpM * 32 + tm * 16 + g;
                const __nv_bfloat16* p = &sPh[r * 72 + kk + 2 * t];
                const __nv_bfloat16* q = &sPl[r * 72 + kk + 2 * t];
                ph[tm][0] = *reinterpret_cast<const unsigned*>(p);
                ph[tm][1] = *reinterpret_cast<const unsigned*>(p + 8 * 72);
                ph[tm][2] = *reinterpret_cast<const unsigned*>(p + 8);
                ph[tm][3] = *reinterpret_cast<const unsigned*>(p + 8 * 72 + 8);
                pl[tm][0] = *reinterpret_cast<const unsigned*>(q);
                pl[tm][1] = *reinterpret_cast<const unsigned*>(q + 8 * 72);
                pl[tm][2] = *reinterpret_cast<const unsigned*>(q + 8);
                pl[tm][3] = *reinterpret_cast<const unsigned*>(q + 8 * 72 + 8);
            }
#pragma unroll
            for (int tn = 0; tn < 4; tn++) {
                int n = warpN * 32 + tn * 8 + g;   // d index
                const __nv_bfloat16* p = &sVh[n * 72 + kk + 2 * t];
                const __nv_bfloat16* q = &sVl[n * 72 + kk + 2 * t];
                vhf[tn][0] = *reinterpret_cast<const unsigned*>(p);
                vhf[tn][1] = *reinterpret_cast<const unsigned*>(p + 8);
                vlf[tn][0] = *reinterpret_cast<const unsigned*>(q);
                vlf[tn][1] = *reinterpret_cast<const unsigned*>(q + 8);
            }
            // term-major ordering
#pragma unroll
            for (int tm = 0; tm < 2; tm++)
#pragma unroll
                for (int tn = 0; tn < 4; tn++)
                    MMA16816(oacc[tm][tn], ph[tm], vhf[tn]);
#pragma unroll
            for (int tm = 0; tm < 2; tm++)
#pragma unroll
                for (int tn = 0; tn < 4; tn++)
                    MMA16816(oacc[tm][tn], ph[tm], vlf[tn]);
#pragma unroll
            for (int tm = 0; tm < 2; tm++)
#pragma unroll
                for (int tn = 0; tn < 4; tn++)
                    MMA16816(oacc[tm][tn], pl[tm], vhf[tn]);
        }
        __syncthreads();
    }

    if (shalf == 0) sAlpha[srow] = 1.f / l_i;
    __syncthreads();

    const int b = bh >> 3, h = bh & 7;
#pragma unroll
    for (int tm = 0; tm < 2; tm++) {
        int r = warpM * 32 + tm * 16 + g;
        float i0 = sAlpha[r], i1 = sAlpha[r + 8];
        int qg0 = qt * 128 + r;
#pragma unroll
        for (int tn = 0; tn < 4; tn++) {
            int d = warpN * 32 + tn * 8 + 2 * t;
            float o00 = oacc[tm][tn][0] * i0, o01 = oacc[tm][tn][1] * i0;
            float o10 = oacc[tm][tn][2] * i1, o11 = oacc[tm][tn][3] * i1;
            __nv_bfloat16 h00 = __float2bfloat16(o00);
            __nv_bfloat16 h01 = __float2bfloat16(o01);
            __nv_bfloat16 h10 = __float2bfloat16(o10);
            __nv_bfloat16 h11 = __float2bfloat16(o11);
            size_t p0 = ((size_t)(b * 1024 + qg0)) * 512 + h * 64 + d;
            size_t p1 = ((size_t)(b * 1024 + qg0 + 8)) * 512 + h * 64 + d;
            *reinterpret_cast<__nv_bfloat162*>(&g_aoh[p0]) = {h00, h01};
            *reinterpret_cast<__nv_bfloat162*>(&g_aoh[p1]) = {h10, h11};
            *reinterpret_cast<__nv_bfloat162*>(&g_aol[p0]) = {
                __float2bfloat16(o00 - __bfloat162float(h00)),
                __float2bfloat16(o01 - __bfloat162float(h01))};
            *reinterpret_cast<__nv_bfloat162*>(&g_aol[p1]) = {
                __float2bfloat16(o10 - __bfloat162float(h10)),
                __float2bfloat16(o11 - __bfloat162float(h11))};
        }
    }
}

// ---------------------------------------------------------------------------
extern "C" void kernel_launch(void* const* d_in, const int* in_sizes, int n_in,
                              void* d_out, int out_size)
{
    const float* x      = (const float*)d_in[0];   // (8,1024,512)
    const float* w_qkv  = (const float*)d_in[1];   // (512,1536)
    const float* temp   = (const float*)d_in[2];   // scalar
    const float* w_out  = (const float*)d_in[3];   // (512,512)
    const float* b_out  = (const float*)d_in[4];   // (512)
    float* out = (float*)d_out;                    // (8,1024,512)

    cudaFuncSetAttribute(attn_kernel,
                         cudaFuncAttributeMaxDynamicSharedMemorySize, ATTN_SMEM);
    cudaFuncSetAttribute(gemm_qkv_kernel,
                         cudaFuncAttributeMaxDynamicSharedMemorySize, GEMM_SMEM);
    cudaFuncSetAttribute(gemm_out_kernel,
                         cudaFuncAttributeMaxDynamicSharedMemorySize, GEMM_SMEM);

    split_x_kernel<<<4096, 256>>>(x);
    split_wT_kernel<<<dim3(48, 16), 256>>>(w_qkv, 1536, 0);
    split_wT_kernel<<<dim3(16, 16), 256>>>(w_out, 512, 1);
    gemm_qkv_kernel<<<dim3(12, 64), 256, GEMM_SMEM>>>();
    attn_kernel<<<dim3(8, 64), 256, ATTN_SMEM>>>(temp);
    gemm_out_kernel<<<dim3(4, 64), 256, GEMM_SMEM>>>(b_out, out);
}